// round 6
// baseline (speedup 1.0000x reference)
#include <cuda_runtime.h>
#include <math.h>

#define NROWS 65536
#define K1 512
#define A3C 64
#define CW 16
#define DT 8
#define PPC 96

typedef unsigned long long ull;

// ---- packed f32x2 helpers (FFMA2: 2 fp32 FMAs per issue slot) ---------------
__device__ __forceinline__ ull ffma2(ull a, ull b, ull c) {
    ull d;
    asm("fma.rn.f32x2 %0, %1, %2, %3;" : "=l"(d) : "l"(a), "l"(b), "l"(c));
    return d;
}
__device__ __forceinline__ ull bcast2(float x) {
    ull d;
    asm("mov.b64 %0, {%1, %1};" : "=l"(d) : "f"(x));
    return d;
}
__device__ __forceinline__ float2 unpack2(ull v) {
    float2 r;
    asm("mov.b64 {%0, %1}, %2;" : "=f"(r.x), "=f"(r.y) : "l"(v));
    return r;
}

// ---------------- scratch (device globals; no runtime allocation) -------------
__device__ float g_t[(size_t)NROWS * A3C];            // normalized t        16 MB
__device__ float g_h[(size_t)DT * NROWS * A3C];       // tower pre-BN h     134 MB
__device__ float g_y[(size_t)DT * NROWS * PPC];       // tower outputs      201 MB
__device__ float g_ps[(size_t)DT * A3C * 512];        // partial sums
__device__ float g_pq[(size_t)DT * A3C * 512];        // partial sumsq
__device__ float g_scale[DT * A3C];                   // rsig*gamma
__device__ float g_shift[DT * A3C];                   // beta - mu*scale

// ---------------- kernel 1: t = normalize(x @ B) ------------------------------
// block: 256 thr, tile 128 rows x 64 cols, K-tiles of 32. reg tile 4x8 (FFMA2).
__global__ __launch_bounds__(256) void k1_gemm_norm(const float* __restrict__ x,
                                                    const float* __restrict__ B) {
    __shared__ __align__(16) float Xs[32 * 129];   // k-major, padded (conflict-free)
    __shared__ __align__(16) float Bs[32 * 64];
    __shared__ float invs[128];
    int tid = threadIdx.x;
    int tx = tid & 7, ty = tid >> 3;          // tx: 8 col-groups of 8, ty: 32 row-groups of 4
    int n0 = blockIdx.x * 128;

    ull acc2[4][4];                            // 4 rows x 4 col-pairs
#pragma unroll
    for (int j = 0; j < 4; j++)
#pragma unroll
        for (int c = 0; c < 4; c++) acc2[j][c] = 0ull;

    for (int kt = 0; kt < 16; kt++) {
        int k0 = kt * 32;
#pragma unroll
        for (int i = 0; i < 4; i++) {
            int l = tid + i * 256;            // 0..1023
            int r = l >> 3, kk4 = l & 7;
            float4 v = *(const float4*)(x + (size_t)(n0 + r) * K1 + k0 + kk4 * 4);
            Xs[(kk4 * 4 + 0) * 129 + r] = v.x;
            Xs[(kk4 * 4 + 1) * 129 + r] = v.y;
            Xs[(kk4 * 4 + 2) * 129 + r] = v.z;
            Xs[(kk4 * 4 + 3) * 129 + r] = v.w;
        }
#pragma unroll
        for (int i = 0; i < 2; i++) {
            int l = tid + i * 256;            // 0..511
            int kk = l >> 4, c4 = l & 15;
            *(float4*)(Bs + kk * 64 + c4 * 4) =
                *(const float4*)(B + (size_t)(k0 + kk) * 64 + c4 * 4);
        }
        __syncthreads();
#pragma unroll
        for (int kk = 0; kk < 32; kk++) {
            ull A[4];
#pragma unroll
            for (int j = 0; j < 4; j++) A[j] = bcast2(Xs[kk * 129 + ty * 4 + j]);
            const ulonglong2* wp = (const ulonglong2*)(Bs + kk * 64 + tx * 8);
            ulonglong2 w01 = wp[0];
            ulonglong2 w23 = wp[1];
            ull wv0 = w01.x, wv1 = w01.y, wv2 = w23.x, wv3 = w23.y;
#pragma unroll
            for (int j = 0; j < 4; j++) {
                acc2[j][0] = ffma2(A[j], wv0, acc2[j][0]);
                acc2[j][1] = ffma2(A[j], wv1, acc2[j][1]);
                acc2[j][2] = ffma2(A[j], wv2, acc2[j][2]);
                acc2[j][3] = ffma2(A[j], wv3, acc2[j][3]);
            }
        }
        __syncthreads();
    }
    // unpack
    float accs[4][8];
#pragma unroll
    for (int j = 0; j < 4; j++)
#pragma unroll
        for (int c = 0; c < 4; c++) {
            float2 u = unpack2(acc2[j][c]);
            accs[j][2 * c] = u.x; accs[j][2 * c + 1] = u.y;
        }
    // row L2-norm reduce across the 8 tx groups (reuse Bs)
    float* ps = Bs;
#pragma unroll
    for (int j = 0; j < 4; j++) {
        float s = 0.f;
#pragma unroll
        for (int c = 0; c < 8; c++) s += accs[j][c] * accs[j][c];
        ps[(ty * 4 + j) * 8 + tx] = s;
    }
    __syncthreads();
    if (tid < 128) {
        float s = 0.f;
#pragma unroll
        for (int q = 0; q < 8; q++) s += ps[tid * 8 + q];
        float nrm = sqrtf(s);
        invs[tid] = 1.f / fmaxf(nrm, 1e-12f);
    }
    __syncthreads();
#pragma unroll
    for (int j = 0; j < 4; j++) {
        int r = ty * 4 + j;
        float inv = invs[r];
        float4 o0, o1;
        o0.x = accs[j][0] * inv; o0.y = accs[j][1] * inv; o0.z = accs[j][2] * inv; o0.w = accs[j][3] * inv;
        o1.x = accs[j][4] * inv; o1.y = accs[j][5] * inv; o1.z = accs[j][6] * inv; o1.w = accs[j][7] * inv;
        *(float4*)(g_t + (size_t)(n0 + r) * 64 + tx * 8)     = o0;
        *(float4*)(g_t + (size_t)(n0 + r) * 64 + tx * 8 + 4) = o1;
    }
}

// ---------------- kernel 2: windowed affine sum -> rep -----------------------
__global__ __launch_bounds__(256) void k2_window(const float* __restrict__ lw,
                                                 const float* __restrict__ lb,
                                                 float* __restrict__ rep) {
    __shared__ float ts[143 * 64];
    int tid = threadIdx.x;
    int a = tid & 63, rg = tid >> 6;          // a: feature, rg: 0..3
    int R0 = blockIdx.x * 128;

    for (int l = tid; l < 143 * 64; l += 256) {
        int s = l >> 6, aa = l & 63;
        int g = R0 - 15 + s;
        ts[l] = (g >= 0) ? g_t[(size_t)g * 64 + aa] : 0.f;
    }
    float w[CW];
    float bs = 0.f;
#pragma unroll
    for (int j = 0; j < CW; j++) { w[j] = lw[j * 64 + a]; bs += lb[j * 64 + a]; }
    __syncthreads();

    for (int m = 0; m < 32; m++) {
        int r = m * 4 + rg;
        int i = R0 + r;
        float acc = bs;
        if (i >= CW - 1) {
#pragma unroll
            for (int j = 0; j < CW; j++) acc += w[j] * ts[(r + j) * 64 + a];
        } else {
#pragma unroll
            for (int j = 0; j < CW; j++) {
                int g = min(j, i);
                acc += w[j] * ts[(g + 15) * 64 + a];
            }
        }
        rep[(size_t)i * 64 + a] = acc;
    }
}

// ---------------- kernel 3: h[d] = rep @ W1[d] + b1[d], + BN partials --------
__global__ __launch_bounds__(256) void k3_gemm_h(const float* __restrict__ rep,
                                                 const float* __restrict__ W1,
                                                 const float* __restrict__ b1) {
    __shared__ __align__(16) float Rs[32 * 129];
    __shared__ __align__(16) float Ws[64 * 64];
    int tid = threadIdx.x;
    int tx = tid & 7, ty = tid >> 3;
    int d = blockIdx.y;
    int n0 = blockIdx.x * 128;

#pragma unroll
    for (int i = 0; i < 4; i++) {
        int l = tid + i * 256;
        *(float4*)(Ws + l * 4) = *(const float4*)(W1 + (size_t)d * 4096 + l * 4);
    }
    ull acc2[4][4];
#pragma unroll
    for (int j = 0; j < 4; j++)
#pragma unroll
        for (int c = 0; c < 4; c++) acc2[j][c] = 0ull;

    for (int kt = 0; kt < 2; kt++) {
        int k0 = kt * 32;
#pragma unroll
        for (int i = 0; i < 4; i++) {
            int l = tid + i * 256;
            int r = l >> 3, kk4 = l & 7;
            float4 v = *(const float4*)(rep + (size_t)(n0 + r) * 64 + k0 + kk4 * 4);
            Rs[(kk4 * 4 + 0) * 129 + r] = v.x;
            Rs[(kk4 * 4 + 1) * 129 + r] = v.y;
            Rs[(kk4 * 4 + 2) * 129 + r] = v.z;
            Rs[(kk4 * 4 + 3) * 129 + r] = v.w;
        }
        __syncthreads();
#pragma unroll
        for (int kk = 0; kk < 32; kk++) {
            ull A[4];
#pragma unroll
            for (int j = 0; j < 4; j++) A[j] = bcast2(Rs[kk * 129 + ty * 4 + j]);
            const ulonglong2* wp = (const ulonglong2*)(Ws + (k0 + kk) * 64 + tx * 8);
            ulonglong2 w01 = wp[0];
            ulonglong2 w23 = wp[1];
            ull wv0 = w01.x, wv1 = w01.y, wv2 = w23.x, wv3 = w23.y;
#pragma unroll
            for (int j = 0; j < 4; j++) {
                acc2[j][0] = ffma2(A[j], wv0, acc2[j][0]);
                acc2[j][1] = ffma2(A[j], wv1, acc2[j][1]);
                acc2[j][2] = ffma2(A[j], wv2, acc2[j][2]);
                acc2[j][3] = ffma2(A[j], wv3, acc2[j][3]);
            }
        }
        __syncthreads();
    }
    float accs[4][8];
#pragma unroll
    for (int j = 0; j < 4; j++)
#pragma unroll
        for (int c = 0; c < 4; c++) {
            float2 u = unpack2(acc2[j][c]);
            accs[j][2 * c] = u.x; accs[j][2 * c + 1] = u.y;
        }
    // epilogue: +b1, write h, BN partial sums
    float bb[8];
#pragma unroll
    for (int c = 0; c < 8; c++) bb[c] = b1[d * 64 + tx * 8 + c];
    float s[8], q[8];
#pragma unroll
    for (int c = 0; c < 8; c++) { s[c] = 0.f; q[c] = 0.f; }
#pragma unroll
    for (int j = 0; j < 4; j++) {
        int r = ty * 4 + j;
        float v0 = accs[j][0] + bb[0], v1 = accs[j][1] + bb[1], v2 = accs[j][2] + bb[2], v3 = accs[j][3] + bb[3];
        float v4 = accs[j][4] + bb[4], v5 = accs[j][5] + bb[5], v6 = accs[j][6] + bb[6], v7 = accs[j][7] + bb[7];
        s[0] += v0; s[1] += v1; s[2] += v2; s[3] += v3; s[4] += v4; s[5] += v5; s[6] += v6; s[7] += v7;
        q[0] += v0*v0; q[1] += v1*v1; q[2] += v2*v2; q[3] += v3*v3;
        q[4] += v4*v4; q[5] += v5*v5; q[6] += v6*v6; q[7] += v7*v7;
        float4 o0, o1;
        o0.x = v0; o0.y = v1; o0.z = v2; o0.w = v3;
        o1.x = v4; o1.y = v5; o1.z = v6; o1.w = v7;
        float* hp = g_h + (size_t)d * NROWS * 64 + (size_t)(n0 + r) * 64 + tx * 8;
        *(float4*)(hp) = o0;
        *(float4*)(hp + 4) = o1;
    }
    float* psum = Rs;            // 2048 floats
    float* psq  = Rs + 2048;     // 2048 floats (Rs has 4128)
#pragma unroll
    for (int c = 0; c < 8; c++) {
        psum[ty * 64 + tx * 8 + c] = s[c];
        psq [ty * 64 + tx * 8 + c] = q[c];
    }
    __syncthreads();
    if (tid < 64) {
        float S = 0.f, Q = 0.f;
#pragma unroll
        for (int t2 = 0; t2 < 32; t2++) { S += psum[t2 * 64 + tid]; Q += psq[t2 * 64 + tid]; }
        g_ps[((size_t)d * 64 + tid) * 512 + blockIdx.x] = S;
        g_pq[((size_t)d * 64 + tid) * 512 + blockIdx.x] = Q;
    }
}

// ---------------- kernel 4: deterministic BN stats reduce --------------------
__global__ __launch_bounds__(128) void k4_stats(const float* __restrict__ gamma,
                                                const float* __restrict__ beta) {
    int id = blockIdx.x;            // d*64 + c
    int tid = threadIdx.x;
    float S = 0.f, Q = 0.f;
    for (int i = tid; i < 512; i += 128) {
        S += g_ps[(size_t)id * 512 + i];
        Q += g_pq[(size_t)id * 512 + i];
    }
    __shared__ float ss[128], qq[128];
    ss[tid] = S; qq[tid] = Q;
    __syncthreads();
    for (int off = 64; off > 0; off >>= 1) {
        if (tid < off) { ss[tid] += ss[tid + off]; qq[tid] += qq[tid + off]; }
        __syncthreads();
    }
    if (tid == 0) {
        float mu  = ss[0] * (1.f / 65536.f);
        float var = qq[0] * (1.f / 65536.f) - mu * mu;
        float rs  = rsqrtf(fmaxf(var, 0.f) + 1e-5f);
        float sc  = rs * gamma[id];
        g_scale[id] = sc;
        g_shift[id] = beta[id] - mu * sc;
    }
}

// ---------------- kernel 5: BN+ELU then y[d] = h' @ W2[d] + b2[d] ------------
__global__ __launch_bounds__(256) void k5_bn_gemm2(const float* __restrict__ W2,
                                                   const float* __restrict__ b2) {
    __shared__ __align__(16) float Hs[32 * 129];
    __shared__ __align__(16) float Ws[64 * 96];
    __shared__ float sA[64], sB[64];
    int tid = threadIdx.x;
    int tx = tid & 15, ty = tid >> 4;   // tx: 16 col-groups of 6, ty: 16 row-groups of 8
    int d = blockIdx.y;
    int n0 = blockIdx.x * 128;

    if (tid < 64) { sA[tid] = g_scale[d * 64 + tid]; sB[tid] = g_shift[d * 64 + tid]; }
#pragma unroll
    for (int i = 0; i < 6; i++) {
        int l = tid + i * 256;
        *(float4*)(Ws + l * 4) = *(const float4*)(W2 + (size_t)d * 6144 + l * 4);
    }
    ull acc2[8][3];                      // 8 rows x 3 col-pairs (6 cols)
#pragma unroll
    for (int j = 0; j < 8; j++)
#pragma unroll
        for (int c = 0; c < 3; c++) acc2[j][c] = 0ull;
    __syncthreads();

    for (int kt = 0; kt < 2; kt++) {
        int k0 = kt * 32;
#pragma unroll
        for (int i = 0; i < 4; i++) {
            int l = tid + i * 256;
            int r = l >> 3, kk4 = l & 7;
            float4 v = *(const float4*)(g_h + (size_t)d * NROWS * 64 +
                                        (size_t)(n0 + r) * 64 + k0 + kk4 * 4);
            int b0 = k0 + kk4 * 4;
            float e;
            e = v.x * sA[b0 + 0] + sB[b0 + 0]; e = e > 0.f ? e : expm1f(e); Hs[(kk4*4+0)*129 + r] = e;
            e = v.y * sA[b0 + 1] + sB[b0 + 1]; e = e > 0.f ? e : expm1f(e); Hs[(kk4*4+1)*129 + r] = e;
            e = v.z * sA[b0 + 2] + sB[b0 + 2]; e = e > 0.f ? e : expm1f(e); Hs[(kk4*4+2)*129 + r] = e;
            e = v.w * sA[b0 + 3] + sB[b0 + 3]; e = e > 0.f ? e : expm1f(e); Hs[(kk4*4+3)*129 + r] = e;
        }
        __syncthreads();
#pragma unroll
        for (int kk = 0; kk < 32; kk++) {
            const ull* wp = (const ull*)(Ws + (k0 + kk) * 96 + tx * 6);   // 8B-aligned (24B steps)
            ull w0 = wp[0], w1 = wp[1], w2 = wp[2];
#pragma unroll
            for (int j = 0; j < 8; j++) {
                ull A = bcast2(Hs[kk * 129 + ty * 8 + j]);
                acc2[j][0] = ffma2(A, w0, acc2[j][0]);
                acc2[j][1] = ffma2(A, w1, acc2[j][1]);
                acc2[j][2] = ffma2(A, w2, acc2[j][2]);
            }
        }
        __syncthreads();
    }
    float bb[6];
#pragma unroll
    for (int c = 0; c < 6; c++) bb[c] = b2[d * 96 + tx * 6 + c];
#pragma unroll
    for (int j = 0; j < 8; j++) {
        int r = ty * 8 + j;
        float* op = g_y + (size_t)d * NROWS * 96 + (size_t)(n0 + r) * 96 + tx * 6;
        float2 u0 = unpack2(acc2[j][0]);
        float2 u1 = unpack2(acc2[j][1]);
        float2 u2 = unpack2(acc2[j][2]);
        float2 o;
        o.x = u0.x + bb[0]; o.y = u0.y + bb[1]; *(float2*)(op)     = o;
        o.x = u1.x + bb[2]; o.y = u1.y + bb[3]; *(float2*)(op + 2) = o;
        o.x = u2.x + bb[4]; o.y = u2.y + bb[5]; *(float2*)(op + 4) = o;
    }
}

// ---------------- kernel 6: interleave y[d][n][p] -> y_1[n][p*8+d] -----------
// plane stride 772 => bank index (4d+p) mod 32: all 32 lanes distinct, conflict-free.
__global__ __launch_bounds__(256) void k6_interleave(float* __restrict__ out) {
    __shared__ float sm[8 * 772];
    int tid = threadIdx.x;
    int n0 = blockIdx.x * 8;
#pragma unroll
    for (int i = 0; i < 24; i++) {
        int l = tid + i * 256;              // 0..6143
        int d = l / 768; int m = l % 768; int n = m / 96; int p = m % 96;
        sm[d * 772 + n * 96 + p] = g_y[(size_t)d * NROWS * 96 + (size_t)(n0 + n) * 96 + p];
    }
    __syncthreads();
#pragma unroll
    for (int i = 0; i < 24; i++) {
        int l = tid + i * 256;
        int n = l / 768; int q = l % 768; int p = q >> 3; int dd = q & 7;
        out[(size_t)(n0 + n) * 768 + q] = sm[dd * 772 + n * 96 + p];
    }
}

// ---------------- launcher ----------------------------------------------------
extern "C" void kernel_launch(void* const* d_in, const int* in_sizes, int n_in,
                              void* d_out, int out_size) {
    const float* x     = (const float*)d_in[0];
    const float* B     = (const float*)d_in[1];
    const float* lw    = (const float*)d_in[2];
    const float* lb    = (const float*)d_in[3];
    const float* W1    = (const float*)d_in[4];
    const float* b1    = (const float*)d_in[5];
    const float* gamma = (const float*)d_in[6];
    const float* beta  = (const float*)d_in[7];
    const float* W2    = (const float*)d_in[8];
    const float* b2    = (const float*)d_in[9];
    // flag (d_in[10]) == 1 and label unused in forward; shapes fix the flag=1 path.

    float* out = (float*)d_out;
    float* rep = out + (size_t)NROWS * (PPC * DT);   // rep section after y_1

    k1_gemm_norm<<<512, 256>>>(x, B);
    k2_window<<<512, 256>>>(lw, lb, rep);
    k3_gemm_h<<<dim3(512, 8), 256>>>(rep, W1, b1);
    k4_stats<<<512, 128>>>(gamma, beta);
    k5_bn_gemm2<<<dim3(512, 8), 256>>>(W2, b2);
    k6_interleave<<<8192, 256>>>(out);
}

// round 7
// speedup vs baseline: 1.1726x; 1.1726x over previous
#include <cuda_runtime.h>
#include <math.h>

#define NROWS 65536
#define K1 512
#define A3C 64
#define CW 16
#define DT 8
#define PPC 96

typedef unsigned int uint;

// ---------------- scratch (device globals; no runtime allocation) -------------
__device__ float g_t[(size_t)NROWS * A3C];            // normalized t        16 MB
__device__ float g_h[(size_t)DT * NROWS * A3C];       // tower pre-BN h     134 MB
__device__ float g_y[(size_t)DT * NROWS * PPC];       // tower outputs      201 MB
__device__ float g_ps[(size_t)DT * A3C * 512];        // partial sums
__device__ float g_pq[(size_t)DT * A3C * 512];        // partial sumsq
__device__ float g_scale[DT * A3C];                   // rsig*gamma
__device__ float g_shift[DT * A3C];                   // beta - mu*scale

// ---- tf32 helpers ------------------------------------------------------------
__device__ __forceinline__ float tf32_hi(float a) {
    float r;
    asm("cvt.rna.tf32.f32 %0, %1;" : "=f"(r) : "f"(a));
    return r;
}
__device__ __forceinline__ void mma_tf32(float* d, const uint* a, const uint* b) {
    asm volatile(
        "mma.sync.aligned.m16n8k8.row.col.f32.tf32.tf32.f32 "
        "{%0,%1,%2,%3}, {%4,%5,%6,%7}, {%8,%9}, {%0,%1,%2,%3};"
        : "+f"(d[0]), "+f"(d[1]), "+f"(d[2]), "+f"(d[3])
        : "r"(a[0]), "r"(a[1]), "r"(a[2]), "r"(a[3]), "r"(b[0]), "r"(b[1]));
}

// ---------------- kernel 1: t = normalize(x @ B), tf32x3 tensor path ----------
// block 128 thr (4 warps), tile 128 rows x 64 cols, K-tiles of 16.
// Warp w covers rows w*32..w*32+31 (2 m-tiles of m16), all 8 n-tiles (n8).
// tf32x3 split: acc += Ahi*Bhi + Ahi*Blo + Alo*Bhi  (lo*lo negligible).
#define KT1 16
#define ASTR 20   // A smem row stride: banks (20*gi+ti)%32 all distinct
#define BSTR 72   // B smem k stride:   banks (8*ti+gi)%32 all distinct
__global__ __launch_bounds__(128) void k1_gemm_norm(const float* __restrict__ x,
                                                    const float* __restrict__ B) {
    __shared__ __align__(16) float Ah[128 * ASTR];   // 10.0 KB
    __shared__ __align__(16) float Al[128 * ASTR];
    __shared__ __align__(16) float Bh[KT1 * BSTR];   //  4.5 KB
    __shared__ __align__(16) float Bl[KT1 * BSTR];
    int tid = threadIdx.x;
    int lane = tid & 31, w = tid >> 5;
    int gi = lane >> 2, ti = lane & 3;
    int n0 = blockIdx.x * 128;

    float d[2][8][4];                 // mt x nt x frag
#pragma unroll
    for (int mt = 0; mt < 2; mt++)
#pragma unroll
        for (int nt = 0; nt < 8; nt++)
#pragma unroll
            for (int q = 0; q < 4; q++) d[mt][nt][q] = 0.f;

    for (int kt = 0; kt < K1 / KT1; kt++) {
        int k0 = kt * KT1;
        // stage A: 128 rows x 16 k = 512 float4, 4 per thread, hi/lo split
#pragma unroll
        for (int i = 0; i < 4; i++) {
            int l = tid + i * 128;              // 0..511
            int r = l >> 2, c4 = l & 3;
            float4 v = *(const float4*)(x + (size_t)(n0 + r) * K1 + k0 + c4 * 4);
            float4 h, lo;
            h.x = tf32_hi(v.x); h.y = tf32_hi(v.y); h.z = tf32_hi(v.z); h.w = tf32_hi(v.w);
            lo.x = v.x - h.x; lo.y = v.y - h.y; lo.z = v.z - h.z; lo.w = v.w - h.w;
            *(float4*)(Ah + r * ASTR + c4 * 4) = h;
            *(float4*)(Al + r * ASTR + c4 * 4) = lo;
        }
        // stage B: 16 k x 64 n = 256 float4, 2 per thread
#pragma unroll
        for (int i = 0; i < 2; i++) {
            int l = tid + i * 128;              // 0..255
            int kk = l >> 4, c4 = l & 15;
            float4 v = *(const float4*)(B + (size_t)(k0 + kk) * 64 + c4 * 4);
            float4 h, lo;
            h.x = tf32_hi(v.x); h.y = tf32_hi(v.y); h.z = tf32_hi(v.z); h.w = tf32_hi(v.w);
            lo.x = v.x - h.x; lo.y = v.y - h.y; lo.z = v.z - h.z; lo.w = v.w - h.w;
            *(float4*)(Bh + kk * BSTR + c4 * 4) = h;
            *(float4*)(Bl + kk * BSTR + c4 * 4) = lo;
        }
        __syncthreads();
#pragma unroll
        for (int ks = 0; ks < KT1 / 8; ks++) {
            int kb = ks * 8;
            uint ah[2][4], al[2][4];
#pragma unroll
            for (int mt = 0; mt < 2; mt++) {
                int r = w * 32 + mt * 16 + gi;
                ah[mt][0] = __float_as_uint(Ah[r * ASTR + kb + ti]);
                ah[mt][1] = __float_as_uint(Ah[(r + 8) * ASTR + kb + ti]);
                ah[mt][2] = __float_as_uint(Ah[r * ASTR + kb + ti + 4]);
                ah[mt][3] = __float_as_uint(Ah[(r + 8) * ASTR + kb + ti + 4]);
                al[mt][0] = __float_as_uint(Al[r * ASTR + kb + ti]);
                al[mt][1] = __float_as_uint(Al[(r + 8) * ASTR + kb + ti]);
                al[mt][2] = __float_as_uint(Al[r * ASTR + kb + ti + 4]);
                al[mt][3] = __float_as_uint(Al[(r + 8) * ASTR + kb + ti + 4]);
            }
            uint bh[8][2], bl[8][2];
#pragma unroll
            for (int nt = 0; nt < 8; nt++) {
                int c = nt * 8 + gi;
                bh[nt][0] = __float_as_uint(Bh[(kb + ti) * BSTR + c]);
                bh[nt][1] = __float_as_uint(Bh[(kb + ti + 4) * BSTR + c]);
                bl[nt][0] = __float_as_uint(Bl[(kb + ti) * BSTR + c]);
                bl[nt][1] = __float_as_uint(Bl[(kb + ti + 4) * BSTR + c]);
            }
#pragma unroll
            for (int mt = 0; mt < 2; mt++)
#pragma unroll
                for (int nt = 0; nt < 8; nt++) {
                    mma_tf32(d[mt][nt], ah[mt], bh[nt]);
                    mma_tf32(d[mt][nt], ah[mt], bl[nt]);
                    mma_tf32(d[mt][nt], al[mt], bh[nt]);
                }
        }
        __syncthreads();
    }
    // epilogue: row L2 normalize + store.
    // lane holds rows (w*32+mt*16+gi, +8), cols (nt*8 + ti*2, +1).
#pragma unroll
    for (int mt = 0; mt < 2; mt++) {
        float s0 = 0.f, s1 = 0.f;
#pragma unroll
        for (int nt = 0; nt < 8; nt++) {
            s0 += d[mt][nt][0] * d[mt][nt][0] + d[mt][nt][1] * d[mt][nt][1];
            s1 += d[mt][nt][2] * d[mt][nt][2] + d[mt][nt][3] * d[mt][nt][3];
        }
        // reduce across the 4 lanes sharing a row (ti = 0..3)
        s0 += __shfl_xor_sync(0xffffffffu, s0, 1);
        s0 += __shfl_xor_sync(0xffffffffu, s0, 2);
        s1 += __shfl_xor_sync(0xffffffffu, s1, 1);
        s1 += __shfl_xor_sync(0xffffffffu, s1, 2);
        float inv0 = 1.f / fmaxf(sqrtf(s0), 1e-12f);
        float inv1 = 1.f / fmaxf(sqrtf(s1), 1e-12f);
        int r0 = n0 + w * 32 + mt * 16 + gi;
#pragma unroll
        for (int nt = 0; nt < 8; nt++) {
            int c = nt * 8 + ti * 2;
            float2 o0, o1;
            o0.x = d[mt][nt][0] * inv0; o0.y = d[mt][nt][1] * inv0;
            o1.x = d[mt][nt][2] * inv1; o1.y = d[mt][nt][3] * inv1;
            *(float2*)(g_t + (size_t)r0 * 64 + c)       = o0;
            *(float2*)(g_t + (size_t)(r0 + 8) * 64 + c) = o1;
        }
    }
}

// ---------------- kernel 2: windowed affine sum -> rep -----------------------
__global__ __launch_bounds__(256) void k2_window(const float* __restrict__ lw,
                                                 const float* __restrict__ lb,
                                                 float* __restrict__ rep) {
    __shared__ float ts[143 * 64];
    int tid = threadIdx.x;
    int a = tid & 63, rg = tid >> 6;          // a: feature, rg: 0..3
    int R0 = blockIdx.x * 128;

    for (int l = tid; l < 143 * 64; l += 256) {
        int s = l >> 6, aa = l & 63;
        int g = R0 - 15 + s;
        ts[l] = (g >= 0) ? g_t[(size_t)g * 64 + aa] : 0.f;
    }
    float w[CW];
    float bs = 0.f;
#pragma unroll
    for (int j = 0; j < CW; j++) { w[j] = lw[j * 64 + a]; bs += lb[j * 64 + a]; }
    __syncthreads();

    for (int m = 0; m < 32; m++) {
        int r = m * 4 + rg;
        int i = R0 + r;
        float acc = bs;
        if (i >= CW - 1) {
#pragma unroll
            for (int j = 0; j < CW; j++) acc += w[j] * ts[(r + j) * 64 + a];
        } else {
#pragma unroll
            for (int j = 0; j < CW; j++) {
                int g = min(j, i);
                acc += w[j] * ts[(g + 15) * 64 + a];
            }
        }
        rep[(size_t)i * 64 + a] = acc;
    }
}

// ---------------- kernel 3: h[d] = rep @ W1[d] + b1[d], + BN partials --------
__global__ __launch_bounds__(256) void k3_gemm_h(const float* __restrict__ rep,
                                                 const float* __restrict__ W1,
                                                 const float* __restrict__ b1) {
    __shared__ __align__(16) float Rs[32 * 129];
    __shared__ __align__(16) float Ws[64 * 64];
    int tid = threadIdx.x;
    int tx = tid & 7, ty = tid >> 3;
    int d = blockIdx.y;
    int n0 = blockIdx.x * 128;

#pragma unroll
    for (int i = 0; i < 4; i++) {
        int l = tid + i * 256;
        *(float4*)(Ws + l * 4) = *(const float4*)(W1 + (size_t)d * 4096 + l * 4);
    }
    float acc[4][8];
#pragma unroll
    for (int j = 0; j < 4; j++)
#pragma unroll
        for (int c = 0; c < 8; c++) acc[j][c] = 0.f;

    for (int kt = 0; kt < 2; kt++) {
        int k0 = kt * 32;
#pragma unroll
        for (int i = 0; i < 4; i++) {
            int l = tid + i * 256;
            int r = l >> 3, kk4 = l & 7;
            float4 v = *(const float4*)(rep + (size_t)(n0 + r) * 64 + k0 + kk4 * 4);
            Rs[(kk4 * 4 + 0) * 129 + r] = v.x;
            Rs[(kk4 * 4 + 1) * 129 + r] = v.y;
            Rs[(kk4 * 4 + 2) * 129 + r] = v.z;
            Rs[(kk4 * 4 + 3) * 129 + r] = v.w;
        }
        __syncthreads();
#pragma unroll
        for (int kk = 0; kk < 32; kk++) {
            float ar[4];
#pragma unroll
            for (int j = 0; j < 4; j++) ar[j] = Rs[kk * 129 + ty * 4 + j];
            float4 b0 = *(const float4*)(Ws + (k0 + kk) * 64 + tx * 8);
            float4 b1v = *(const float4*)(Ws + (k0 + kk) * 64 + tx * 8 + 4);
#pragma unroll
            for (int j = 0; j < 4; j++) {
                acc[j][0] += ar[j] * b0.x;  acc[j][1] += ar[j] * b0.y;
                acc[j][2] += ar[j] * b0.z;  acc[j][3] += ar[j] * b0.w;
                acc[j][4] += ar[j] * b1v.x; acc[j][5] += ar[j] * b1v.y;
                acc[j][6] += ar[j] * b1v.z; acc[j][7] += ar[j] * b1v.w;
            }
        }
        __syncthreads();
    }
    // epilogue: +b1, write h, BN partial sums
    float bb[8];
#pragma unroll
    for (int c = 0; c < 8; c++) bb[c] = b1[d * 64 + tx * 8 + c];
    float s[8], q[8];
#pragma unroll
    for (int c = 0; c < 8; c++) { s[c] = 0.f; q[c] = 0.f; }
#pragma unroll
    for (int j = 0; j < 4; j++) {
        int r = ty * 4 + j;
        float v0 = acc[j][0] + bb[0], v1 = acc[j][1] + bb[1], v2 = acc[j][2] + bb[2], v3 = acc[j][3] + bb[3];
        float v4 = acc[j][4] + bb[4], v5 = acc[j][5] + bb[5], v6 = acc[j][6] + bb[6], v7 = acc[j][7] + bb[7];
        s[0] += v0; s[1] += v1; s[2] += v2; s[3] += v3; s[4] += v4; s[5] += v5; s[6] += v6; s[7] += v7;
        q[0] += v0*v0; q[1] += v1*v1; q[2] += v2*v2; q[3] += v3*v3;
        q[4] += v4*v4; q[5] += v5*v5; q[6] += v6*v6; q[7] += v7*v7;
        float4 o0, o1;
        o0.x = v0; o0.y = v1; o0.z = v2; o0.w = v3;
        o1.x = v4; o1.y = v5; o1.z = v6; o1.w = v7;
        float* hp = g_h + (size_t)d * NROWS * 64 + (size_t)(n0 + r) * 64 + tx * 8;
        *(float4*)(hp) = o0;
        *(float4*)(hp + 4) = o1;
    }
    float* psum = Rs;            // 2048 floats
    float* psq  = Rs + 2048;     // 2048 floats (Rs has 4128)
#pragma unroll
    for (int c = 0; c < 8; c++) {
        psum[ty * 64 + tx * 8 + c] = s[c];
        psq [ty * 64 + tx * 8 + c] = q[c];
    }
    __syncthreads();
    if (tid < 64) {
        float S = 0.f, Q = 0.f;
#pragma unroll
        for (int t2 = 0; t2 < 32; t2++) { S += psum[t2 * 64 + tid]; Q += psq[t2 * 64 + tid]; }
        g_ps[((size_t)d * 64 + tid) * 512 + blockIdx.x] = S;
        g_pq[((size_t)d * 64 + tid) * 512 + blockIdx.x] = Q;
    }
}

// ---------------- kernel 4: deterministic BN stats reduce --------------------
__global__ __launch_bounds__(128) void k4_stats(const float* __restrict__ gamma,
                                                const float* __restrict__ beta) {
    int id = blockIdx.x;            // d*64 + c
    int tid = threadIdx.x;
    float S = 0.f, Q = 0.f;
    for (int i = tid; i < 512; i += 128) {
        S += g_ps[(size_t)id * 512 + i];
        Q += g_pq[(size_t)id * 512 + i];
    }
    __shared__ float ss[128], qq[128];
    ss[tid] = S; qq[tid] = Q;
    __syncthreads();
    for (int off = 64; off > 0; off >>= 1) {
        if (tid < off) { ss[tid] += ss[tid + off]; qq[tid] += qq[tid + off]; }
        __syncthreads();
    }
    if (tid == 0) {
        float mu  = ss[0] * (1.f / 65536.f);
        float var = qq[0] * (1.f / 65536.f) - mu * mu;
        float rs  = rsqrtf(fmaxf(var, 0.f) + 1e-5f);
        float sc  = rs * gamma[id];
        g_scale[id] = sc;
        g_shift[id] = beta[id] - mu * sc;
    }
}

// ---------------- kernel 5: BN+ELU then y[d] = h' @ W2[d] + b2[d] ------------
__global__ __launch_bounds__(256) void k5_bn_gemm2(const float* __restrict__ W2,
                                                   const float* __restrict__ b2) {
    __shared__ __align__(16) float Hs[32 * 129];
    __shared__ __align__(16) float Ws[64 * 96];
    __shared__ float sA[64], sB[64];
    int tid = threadIdx.x;
    int tx = tid & 15, ty = tid >> 4;   // tx: 16 col-groups of 6, ty: 16 row-groups of 8
    int d = blockIdx.y;
    int n0 = blockIdx.x * 128;

    if (tid < 64) { sA[tid] = g_scale[d * 64 + tid]; sB[tid] = g_shift[d * 64 + tid]; }
#pragma unroll
    for (int i = 0; i < 6; i++) {
        int l = tid + i * 256;
        *(float4*)(Ws + l * 4) = *(const float4*)(W2 + (size_t)d * 6144 + l * 4);
    }
    float acc[8][6];
#pragma unroll
    for (int j = 0; j < 8; j++)
#pragma unroll
        for (int c = 0; c < 6; c++) acc[j][c] = 0.f;
    __syncthreads();

    for (int kt = 0; kt < 2; kt++) {
        int k0 = kt * 32;
#pragma unroll
        for (int i = 0; i < 4; i++) {
            int l = tid + i * 256;
            int r = l >> 3, kk4 = l & 7;
            float4 v = *(const float4*)(g_h + (size_t)d * NROWS * 64 +
                                        (size_t)(n0 + r) * 64 + k0 + kk4 * 4);
            int b0 = k0 + kk4 * 4;
            float e;
            e = v.x * sA[b0 + 0] + sB[b0 + 0]; e = e > 0.f ? e : expm1f(e); Hs[(kk4*4+0)*129 + r] = e;
            e = v.y * sA[b0 + 1] + sB[b0 + 1]; e = e > 0.f ? e : expm1f(e); Hs[(kk4*4+1)*129 + r] = e;
            e = v.z * sA[b0 + 2] + sB[b0 + 2]; e = e > 0.f ? e : expm1f(e); Hs[(kk4*4+2)*129 + r] = e;
            e = v.w * sA[b0 + 3] + sB[b0 + 3]; e = e > 0.f ? e : expm1f(e); Hs[(kk4*4+3)*129 + r] = e;
        }
        __syncthreads();
#pragma unroll
        for (int kk = 0; kk < 32; kk++) {
            float ar[8];
#pragma unroll
            for (int j = 0; j < 8; j++) ar[j] = Hs[kk * 129 + ty * 8 + j];
            const float* wp = Ws + (k0 + kk) * 96 + tx * 6;
            float2 w0 = *(const float2*)(wp);
            float2 w1 = *(const float2*)(wp + 2);
            float2 w2 = *(const float2*)(wp + 4);
#pragma unroll
            for (int j = 0; j < 8; j++) {
                acc[j][0] += ar[j] * w0.x; acc[j][1] += ar[j] * w0.y;
                acc[j][2] += ar[j] * w1.x; acc[j][3] += ar[j] * w1.y;
                acc[j][4] += ar[j] * w2.x; acc[j][5] += ar[j] * w2.y;
            }
        }
        __syncthreads();
    }
    float bb[6];
#pragma unroll
    for (int c = 0; c < 6; c++) bb[c] = b2[d * 96 + tx * 6 + c];
#pragma unroll
    for (int j = 0; j < 8; j++) {
        int r = ty * 8 + j;
        float* op = g_y + (size_t)d * NROWS * 96 + (size_t)(n0 + r) * 96 + tx * 6;
        float2 o;
        o.x = acc[j][0] + bb[0]; o.y = acc[j][1] + bb[1]; *(float2*)(op)     = o;
        o.x = acc[j][2] + bb[2]; o.y = acc[j][3] + bb[3]; *(float2*)(op + 2) = o;
        o.x = acc[j][4] + bb[4]; o.y = acc[j][5] + bb[5]; *(float2*)(op + 4) = o;
    }
}

// ---------------- kernel 6: interleave y[d][n][p] -> y_1[n][p*8+d] -----------
// plane stride 772 => bank index (4d+p) mod 32: all 32 lanes distinct, conflict-free.
__global__ __launch_bounds__(256) void k6_interleave(float* __restrict__ out) {
    __shared__ float sm[8 * 772];
    int tid = threadIdx.x;
    int n0 = blockIdx.x * 8;
#pragma unroll
    for (int i = 0; i < 24; i++) {
        int l = tid + i * 256;              // 0..6143
        int d = l / 768; int m = l % 768; int n = m / 96; int p = m % 96;
        sm[d * 772 + n * 96 + p] = g_y[(size_t)d * NROWS * 96 + (size_t)(n0 + n) * 96 + p];
    }
    __syncthreads();
#pragma unroll
    for (int i = 0; i < 24; i++) {
        int l = tid + i * 256;
        int n = l / 768; int q = l % 768; int p = q >> 3; int dd = q & 7;
        out[(size_t)(n0 + n) * 768 + q] = sm[dd * 772 + n * 96 + p];
    }
}

// ---------------- launcher ----------------------------------------------------
extern "C" void kernel_launch(void* const* d_in, const int* in_sizes, int n_in,
                              void* d_out, int out_size) {
    const float* x     = (const float*)d_in[0];
    const float* B     = (const float*)d_in[1];
    const float* lw    = (const float*)d_in[2];
    const float* lb    = (const float*)d_in[3];
    const float* W1    = (const float*)d_in[4];
    const float* b1    = (const float*)d_in[5];
    const float* gamma = (const float*)d_in[6];
    const float* beta  = (const float*)d_in[7];
    const float* W2    = (const float*)d_in[8];
    const float* b2    = (const float*)d_in[9];
    // flag (d_in[10]) == 1 and label unused in forward; shapes fix the flag=1 path.

    float* out = (float*)d_out;
    float* rep = out + (size_t)NROWS * (PPC * DT);   // rep section after y_1

    k1_gemm_norm<<<512, 128>>>(x, B);
    k2_window<<<512, 256>>>(lw, lb, rep);
    k3_gemm_h<<<dim3(512, 8), 256>>>(rep, W1, b1);
    k4_stats<<<512, 128>>>(gamma, beta);
    k5_bn_gemm2<<<dim3(512, 8), 256>>>(W2, b2);
    k6_interleave<<<8192, 256>>>(out);
}

// round 11
// speedup vs baseline: 1.5603x; 1.3306x over previous
#include <cuda_runtime.h>
#include <math.h>

#define NROWS 65536
#define K1 512
#define A3C 64
#define CW 16
#define DT 8
#define PPC 96
#define NBLK_COV 256         // blocks in covariance pass (256 rows each)

// ---------------- scratch (device globals; no runtime allocation) -------------
__device__ float g_t[(size_t)NROWS * A3C];              // normalized t   16 MB
__device__ float g_y[(size_t)DT * NROWS * PPC];         // tower outputs 201 MB
__device__ float g_cp[(size_t)NBLK_COV * A3C * A3C];    // C partials      4 MB
__device__ float g_cm[(size_t)NBLK_COV * A3C];          // m partials
__device__ float g_C[A3C * A3C];                        // C = rep^T rep (sums)
__device__ float g_m[A3C];                              // column sums
__device__ float g_scale[DT * A3C];                     // gamma * rsqrt(var+eps)
__device__ float g_shift[DT * A3C];                     // beta - E[g]*scale

// ---------------- kernel 1: t = normalize(x @ B)  (R3, proven) ---------------
__global__ __launch_bounds__(256) void k1_gemm_norm(const float* __restrict__ x,
                                                    const float* __restrict__ B) {
    __shared__ __align__(16) float Xs[32 * 129];
    __shared__ __align__(16) float Bs[32 * 64];
    __shared__ float invs[128];
    int tid = threadIdx.x;
    int tx = tid & 7, ty = tid >> 3;
    int n0 = blockIdx.x * 128;

    float acc[4][8];
#pragma unroll
    for (int j = 0; j < 4; j++)
#pragma unroll
        for (int c = 0; c < 8; c++) acc[j][c] = 0.f;

    for (int kt = 0; kt < 16; kt++) {
        int k0 = kt * 32;
#pragma unroll
        for (int i = 0; i < 4; i++) {
            int l = tid + i * 256;
            int r = l >> 3, kk4 = l & 7;
            float4 v = *(const float4*)(x + (size_t)(n0 + r) * K1 + k0 + kk4 * 4);
            Xs[(kk4 * 4 + 0) * 129 + r] = v.x;
            Xs[(kk4 * 4 + 1) * 129 + r] = v.y;
            Xs[(kk4 * 4 + 2) * 129 + r] = v.z;
            Xs[(kk4 * 4 + 3) * 129 + r] = v.w;
        }
#pragma unroll
        for (int i = 0; i < 2; i++) {
            int l = tid + i * 256;
            int kk = l >> 4, c4 = l & 15;
            *(float4*)(Bs + kk * 64 + c4 * 4) =
                *(const float4*)(B + (size_t)(k0 + kk) * 64 + c4 * 4);
        }
        __syncthreads();
#pragma unroll
        for (int kk = 0; kk < 32; kk++) {
            float ar[4];
#pragma unroll
            for (int j = 0; j < 4; j++) ar[j] = Xs[kk * 129 + ty * 4 + j];
            float4 b0 = *(const float4*)(Bs + kk * 64 + tx * 8);
            float4 b1 = *(const float4*)(Bs + kk * 64 + tx * 8 + 4);
#pragma unroll
            for (int j = 0; j < 4; j++) {
                acc[j][0] += ar[j] * b0.x; acc[j][1] += ar[j] * b0.y;
                acc[j][2] += ar[j] * b0.z; acc[j][3] += ar[j] * b0.w;
                acc[j][4] += ar[j] * b1.x; acc[j][5] += ar[j] * b1.y;
                acc[j][6] += ar[j] * b1.z; acc[j][7] += ar[j] * b1.w;
            }
        }
        __syncthreads();
    }
    float* ps = Bs;
#pragma unroll
    for (int j = 0; j < 4; j++) {
        float s = 0.f;
#pragma unroll
        for (int c = 0; c < 8; c++) s += acc[j][c] * acc[j][c];
        ps[(ty * 4 + j) * 8 + tx] = s;
    }
    __syncthreads();
    if (tid < 128) {
        float s = 0.f;
#pragma unroll
        for (int q = 0; q < 8; q++) s += ps[tid * 8 + q];
        invs[tid] = 1.f / fmaxf(sqrtf(s), 1e-12f);
    }
    __syncthreads();
#pragma unroll
    for (int j = 0; j < 4; j++) {
        int r = ty * 4 + j;
        float inv = invs[r];
        float4 o0, o1;
        o0.x = acc[j][0] * inv; o0.y = acc[j][1] * inv; o0.z = acc[j][2] * inv; o0.w = acc[j][3] * inv;
        o1.x = acc[j][4] * inv; o1.y = acc[j][5] * inv; o1.z = acc[j][6] * inv; o1.w = acc[j][7] * inv;
        *(float4*)(g_t + (size_t)(n0 + r) * 64 + tx * 8)     = o0;
        *(float4*)(g_t + (size_t)(n0 + r) * 64 + tx * 8 + 4) = o1;
    }
}

// ---------------- kernel 2: windowed affine sum -> rep  (R3, proven) ---------
__global__ __launch_bounds__(256) void k2_window(const float* __restrict__ lw,
                                                 const float* __restrict__ lb,
                                                 float* __restrict__ rep) {
    __shared__ float ts[143 * 64];
    int tid = threadIdx.x;
    int a = tid & 63, rg = tid >> 6;
    int R0 = blockIdx.x * 128;

    for (int l = tid; l < 143 * 64; l += 256) {
        int s = l >> 6, aa = l & 63;
        int g = R0 - 15 + s;
        ts[l] = (g >= 0) ? g_t[(size_t)g * 64 + aa] : 0.f;
    }
    float w[CW];
    float bs = 0.f;
#pragma unroll
    for (int j = 0; j < CW; j++) { w[j] = lw[j * 64 + a]; bs += lb[j * 64 + a]; }
    __syncthreads();

    for (int m = 0; m < 32; m++) {
        int r = m * 4 + rg;
        int i = R0 + r;
        float acc = bs;
        if (i >= CW - 1) {
#pragma unroll
            for (int j = 0; j < CW; j++) acc += w[j] * ts[(r + j) * 64 + a];
        } else {
#pragma unroll
            for (int j = 0; j < CW; j++) {
                int g = min(j, i);
                acc += w[j] * ts[(g + 15) * 64 + a];
            }
        }
        rep[(size_t)i * 64 + a] = acc;
    }
}

// ---------------- kernel 3c: C = rep^T rep partials + column sums ------------
__global__ __launch_bounds__(256) void k3_cov(const float* __restrict__ rep) {
    __shared__ __align__(16) float ts[32 * 68];
    int tid = threadIdx.x;
    int p = tid >> 4, q = tid & 15;
    int a0 = p * 4, b0 = q * 4;
    size_t R0 = (size_t)blockIdx.x * 256;

    float acc[4][4];
#pragma unroll
    for (int i = 0; i < 4; i++)
#pragma unroll
        for (int j = 0; j < 4; j++) acc[i][j] = 0.f;
    float msum = 0.f;

    for (int chunk = 0; chunk < 8; chunk++) {
#pragma unroll
        for (int i = 0; i < 2; i++) {
            int idx = tid + i * 256;            // 0..511 float4s
            int row = idx >> 4, c4 = idx & 15;
            float4 v = *(const float4*)(rep + (R0 + chunk * 32 + row) * 64 + c4 * 4);
            *(float4*)(ts + row * 68 + c4 * 4) = v;
        }
        __syncthreads();
#pragma unroll 4
        for (int k = 0; k < 32; k++) {
            float4 ta = *(const float4*)(ts + k * 68 + a0);
            float4 tb = *(const float4*)(ts + k * 68 + b0);
            acc[0][0] += ta.x * tb.x; acc[0][1] += ta.x * tb.y; acc[0][2] += ta.x * tb.z; acc[0][3] += ta.x * tb.w;
            acc[1][0] += ta.y * tb.x; acc[1][1] += ta.y * tb.y; acc[1][2] += ta.y * tb.z; acc[1][3] += ta.y * tb.w;
            acc[2][0] += ta.z * tb.x; acc[2][1] += ta.z * tb.y; acc[2][2] += ta.z * tb.z; acc[2][3] += ta.z * tb.w;
            acc[3][0] += ta.w * tb.x; acc[3][1] += ta.w * tb.y; acc[3][2] += ta.w * tb.z; acc[3][3] += ta.w * tb.w;
        }
        if (tid < 64) {
#pragma unroll 8
            for (int k = 0; k < 32; k++) msum += ts[k * 68 + tid];
        }
        __syncthreads();
    }
    float* cp = g_cp + (size_t)blockIdx.x * 4096;
#pragma unroll
    for (int i = 0; i < 4; i++)
#pragma unroll
        for (int j = 0; j < 4; j++)
            cp[(a0 + i) * 64 + (b0 + j)] = acc[i][j];
    if (tid < 64) g_cm[(size_t)blockIdx.x * 64 + tid] = msum;
}

// ---------------- kernel 4a: reduce partials -> g_C, g_m ---------------------
__global__ __launch_bounds__(256) void k4a_reduce() {
    int idx = blockIdx.x * 256 + threadIdx.x;
    if (idx < 4096) {
        float s = 0.f;
        for (int pb = 0; pb < NBLK_COV; pb++) s += g_cp[(size_t)pb * 4096 + idx];
        g_C[idx] = s;
    } else if (idx < 4096 + 64) {
        int a = idx - 4096;
        float s = 0.f;
        for (int pb = 0; pb < NBLK_COV; pb++) s += g_cm[(size_t)pb * 64 + a];
        g_m[a] = s;
    }
}

// ---------------- kernel 4b: analytic BN scale/shift per (d,b) ---------------
// var(h) = var(g) with g = rep@W1 (b1 cancels in BN centering).
__global__ __launch_bounds__(256) void k4b_stats(const float* __restrict__ W1,
                                                 const float* __restrict__ gamma,
                                                 const float* __restrict__ beta) {
    __shared__ float Cs[64 * 65];
    __shared__ float Ws1[4096];
    __shared__ float sm_m[64];
    __shared__ float mq[256], me[256];
    int tid = threadIdx.x;
    int b = tid & 63, part = tid >> 6;
    int d = blockIdx.x;

    for (int idx = tid; idx < 4096; idx += 256) {
        int a = idx >> 6, a2 = idx & 63;
        Cs[a * 65 + a2] = g_C[idx];
        Ws1[idx] = W1[(size_t)d * 4096 + idx];
    }
    if (tid < 64) sm_m[tid] = g_m[tid];
    __syncthreads();

    float qp = 0.f, ep = 0.f;
    int aBeg = part * 16;
#pragma unroll 2
    for (int a = aBeg; a < aBeg + 16; a++) {
        float wa = Ws1[a * 64 + b];
        float ta = 0.f;
#pragma unroll 8
        for (int a2 = 0; a2 < 64; a2++) ta += Cs[a * 65 + a2] * Ws1[a2 * 64 + b];
        qp += wa * ta;
        ep += sm_m[a] * wa;
    }
    mq[tid] = qp; me[tid] = ep;
    __syncthreads();
    if (part == 0) {
        const float invN = 1.f / 65536.f;
        float q  = mq[b] + mq[b + 64] + mq[b + 128] + mq[b + 192];
        float eg = (me[b] + me[b + 64] + me[b + 128] + me[b + 192]) * invN;
        float var = q * invN - eg * eg;
        float sc = gamma[d * 64 + b] * rsqrtf(fmaxf(var, 0.f) + 1e-5f);
        g_scale[d * 64 + b] = sc;
        g_shift[d * 64 + b] = beta[d * 64 + b] - eg * sc;
    }
}

// ---------------- kernel 5f: fused  g=rep@W1 -> BN+ELU -> y=h'@W2+b2 ---------
// smem: Ws 3072f (W1 in 2 halves of 2048, W2 in 2 halves of 3072)
//       HR 64*129f (Rs staging uses first 32*129, then h' k-major [64][128])
// total 3072+8256 = 11328 floats = 45312 B < 48K static.
#define HSTR 129
__global__ __launch_bounds__(256) void k5_fused(const float* __restrict__ rep,
                                               const float* __restrict__ W1,
                                               const float* __restrict__ W2,
                                               const float* __restrict__ b2) {
    __shared__ __align__(16) float Ws[3072];
    __shared__ __align__(16) float HR[64 * HSTR];
    int tid = threadIdx.x;
    int tx = tid & 7, ty = tid >> 3;
    int d = blockIdx.y;
    int n0 = blockIdx.x * 128;

    float sc[8], sh[8];
#pragma unroll
    for (int c = 0; c < 8; c++) {
        sc[c] = g_scale[d * 64 + tx * 8 + c];
        sh[c] = g_shift[d * 64 + tx * 8 + c];
    }
    float acc[4][8];
#pragma unroll
    for (int j = 0; j < 4; j++)
#pragma unroll
        for (int c = 0; c < 8; c++) acc[j][c] = 0.f;

    // ---- GEMM1: g = rep @ W1 (no bias; b1 cancels in BN). W1 staged per-half.
    for (int kt = 0; kt < 2; kt++) {
        int k0 = kt * 32;
#pragma unroll
        for (int i = 0; i < 4; i++) {
            int l = tid + i * 256;
            int r = l >> 3, kk4 = l & 7;
            float4 v = *(const float4*)(rep + (size_t)(n0 + r) * 64 + k0 + kk4 * 4);
            HR[(kk4 * 4 + 0) * HSTR + r] = v.x;
            HR[(kk4 * 4 + 1) * HSTR + r] = v.y;
            HR[(kk4 * 4 + 2) * HSTR + r] = v.z;
            HR[(kk4 * 4 + 3) * HSTR + r] = v.w;
        }
        // stage W1 rows k0..k0+31 (2048 floats = 512 float4)
#pragma unroll
        for (int i = 0; i < 2; i++) {
            int l = tid + i * 256;
            *(float4*)(Ws + l * 4) = *(const float4*)(W1 + (size_t)d * 4096 + k0 * 64 + l * 4);
        }
        __syncthreads();
#pragma unroll
        for (int kk = 0; kk < 32; kk++) {
            float ar[4];
#pragma unroll
            for (int j = 0; j < 4; j++) ar[j] = HR[kk * HSTR + ty * 4 + j];
            float4 w0 = *(const float4*)(Ws + kk * 64 + tx * 8);
            float4 w1 = *(const float4*)(Ws + kk * 64 + tx * 8 + 4);
#pragma unroll
            for (int j = 0; j < 4; j++) {
                acc[j][0] += ar[j] * w0.x; acc[j][1] += ar[j] * w0.y;
                acc[j][2] += ar[j] * w0.z; acc[j][3] += ar[j] * w0.w;
                acc[j][4] += ar[j] * w1.x; acc[j][5] += ar[j] * w1.y;
                acc[j][6] += ar[j] * w1.z; acc[j][7] += ar[j] * w1.w;
            }
        }
        __syncthreads();
    }

    // ---- BN + ELU in regs, write h' k-major [feature 64][row 128] into HR ----
    // bank = (8tx + c + 4ty + j) % 32 -> 2-way conflicts max.
#pragma unroll
    for (int c = 0; c < 8; c++)
#pragma unroll
        for (int j = 0; j < 4; j++) {
            float v = acc[j][c] * sc[c] + sh[c];
            v = v > 0.f ? v : expm1f(v);
            HR[(tx * 8 + c) * HSTR + ty * 4 + j] = v;
        }
    // stage W2 half 0 (k-rows 0..31 of [64 k][96 p])
#pragma unroll
    for (int i = 0; i < 3; i++) {
        int l = tid + i * 256;
        *(float4*)(Ws + l * 4) = *(const float4*)(W2 + (size_t)d * 6144 + l * 4);
    }
    __syncthreads();

    // ---- GEMM2: y = h' @ W2 + b2 ----
    int tx2 = tid & 15, ty2 = tid >> 4;
    float acc2[8][6];
#pragma unroll
    for (int j = 0; j < 8; j++)
#pragma unroll
        for (int c = 0; c < 6; c++) acc2[j][c] = 0.f;

#pragma unroll
    for (int half = 0; half < 2; half++) {
        if (half == 1) {
            __syncthreads();
#pragma unroll
            for (int i = 0; i < 3; i++) {
                int l = tid + i * 256;
                *(float4*)(Ws + l * 4) = *(const float4*)(W2 + (size_t)d * 6144 + 3072 + l * 4);
            }
            __syncthreads();
        }
#pragma unroll
        for (int kk = 0; kk < 32; kk++) {
            int kkg = half * 32 + kk;
            float ar[8];
#pragma unroll
            for (int j = 0; j < 8; j++) ar[j] = HR[kkg * HSTR + ty2 * 8 + j];
            const float* wp = Ws + kk * 96 + tx2 * 6;
            float2 w0 = *(const float2*)(wp);
            float2 w1 = *(const float2*)(wp + 2);
            float2 w2v = *(const float2*)(wp + 4);
#pragma unroll
            for (int j = 0; j < 8; j++) {
                acc2[j][0] += ar[j] * w0.x;  acc2[j][1] += ar[j] * w0.y;
                acc2[j][2] += ar[j] * w1.x;  acc2[j][3] += ar[j] * w1.y;
                acc2[j][4] += ar[j] * w2v.x; acc2[j][5] += ar[j] * w2v.y;
            }
        }
    }
    float bb[6];
#pragma unroll
    for (int c = 0; c < 6; c++) bb[c] = b2[d * 96 + tx2 * 6 + c];
#pragma unroll
    for (int j = 0; j < 8; j++) {
        int r = ty2 * 8 + j;
        float* op = g_y + (size_t)d * NROWS * 96 + (size_t)(n0 + r) * 96 + tx2 * 6;
        float2 o;
        o.x = acc2[j][0] + bb[0]; o.y = acc2[j][1] + bb[1]; *(float2*)(op)     = o;
        o.x = acc2[j][2] + bb[2]; o.y = acc2[j][3] + bb[3]; *(float2*)(op + 2) = o;
        o.x = acc2[j][4] + bb[4]; o.y = acc2[j][5] + bb[5]; *(float2*)(op + 4) = o;
    }
}

// ---------------- kernel 6: interleave y[d][n][p] -> y_1[n][p*8+d]  (R3) -----
__global__ __launch_bounds__(256) void k6_interleave(float* __restrict__ out) {
    __shared__ float sm[8 * 772];
    int tid = threadIdx.x;
    int n0 = blockIdx.x * 8;
#pragma unroll
    for (int i = 0; i < 24; i++) {
        int l = tid + i * 256;
        int d = l / 768; int m = l % 768; int n = m / 96; int p = m % 96;
        sm[d * 772 + n * 96 + p] = g_y[(size_t)d * NROWS * 96 + (size_t)(n0 + n) * 96 + p];
    }
    __syncthreads();
#pragma unroll
    for (int i = 0; i < 24; i++) {
        int l = tid + i * 256;
        int n = l / 768; int q = l % 768; int p = q >> 3; int dd = q & 7;
        out[(size_t)(n0 + n) * 768 + q] = sm[dd * 772 + n * 96 + p];
    }
}

// ---------------- launcher ----------------------------------------------------
extern "C" void kernel_launch(void* const* d_in, const int* in_sizes, int n_in,
                              void* d_out, int out_size) {
    const float* x     = (const float*)d_in[0];
    const float* B     = (const float*)d_in[1];
    const float* lw    = (const float*)d_in[2];
    const float* lb    = (const float*)d_in[3];
    const float* W1    = (const float*)d_in[4];
    // d_in[5] = b1: cancels exactly inside train-mode BatchNorm (h - mu); unused.
    const float* gamma = (const float*)d_in[6];
    const float* beta  = (const float*)d_in[7];
    const float* W2    = (const float*)d_in[8];
    const float* b2    = (const float*)d_in[9];

    float* out = (float*)d_out;
    float* rep = out + (size_t)NROWS * (PPC * DT);   // rep section after y_1

    k1_gemm_norm<<<512, 256>>>(x, B);
    k2_window<<<512, 256>>>(lw, lb, rep);
    k3_cov<<<NBLK_COV, 256>>>(rep);
    k4a_reduce<<<17, 256>>>();
    k4b_stats<<<DT, 256>>>(W1, gamma, beta);
    k5_fused<<<dim3(512, DT), 256>>>(rep, W1, W2, b2);
    k6_interleave<<<8192, 256>>>(out);
}